// round 12
// baseline (speedup 1.0000x reference)
#include <cuda_runtime.h>
#include <cuda_fp16.h>

// FullAttention: causal MHA, B=4, L=2048, H=16, DK=64, fp32 I/O.
// Round 9: BM=64 / 4-warp CTAs (4 CTAs/SM, decorrelated barriers),
//          reversed grid for causal load balance. Math identical to R7.

constexpr int Bc = 4, Lc = 2048, Hc = 16, Dc = 64;
constexpr int BM = 64;      // query rows per CTA
constexpr int BN = 64;      // key rows per iteration
constexpr int NT = 128;     // 4 warps
constexpr int SKH = 72;     // smem row stride in halfs (144 B)
constexpr float LOG2E = 1.44269504f;

// fp16 copies of K and V, produced once per launch by convert_kv.
__device__ __half gK[(size_t)Bc * Lc * Hc * Dc];
__device__ __half gV[(size_t)Bc * Lc * Hc * Dc];

__device__ __forceinline__ unsigned sptr(const void* p) {
    return (unsigned)__cvta_generic_to_shared(p);
}
__device__ __forceinline__ void ldsm4(unsigned r[4], unsigned addr) {
    asm volatile("ldmatrix.sync.aligned.m8n8.x4.shared.b16 {%0,%1,%2,%3}, [%4];"
                 : "=r"(r[0]), "=r"(r[1]), "=r"(r[2]), "=r"(r[3]) : "r"(addr));
}
__device__ __forceinline__ void ldsm4t(unsigned r[4], unsigned addr) {
    asm volatile("ldmatrix.sync.aligned.m8n8.x4.trans.shared.b16 {%0,%1,%2,%3}, [%4];"
                 : "=r"(r[0]), "=r"(r[1]), "=r"(r[2]), "=r"(r[3]) : "r"(addr));
}
// fp32-accum mma (GEMM2 / row sums)
__device__ __forceinline__ void mma_f16(float c[4], const unsigned a[4], const unsigned b[2]) {
    asm volatile(
        "mma.sync.aligned.m16n8k16.row.col.f32.f16.f16.f32 "
        "{%0,%1,%2,%3}, {%4,%5,%6,%7}, {%8,%9}, {%0,%1,%2,%3};"
        : "+f"(c[0]), "+f"(c[1]), "+f"(c[2]), "+f"(c[3])
        : "r"(a[0]), "r"(a[1]), "r"(a[2]), "r"(a[3]), "r"(b[0]), "r"(b[1]));
}
// fp16-accum mma (GEMM1): c/d packed half2 pairs in a-frag layout
__device__ __forceinline__ void mma_f16h(unsigned c[2], const unsigned a[4], const unsigned b[2]) {
    asm volatile(
        "mma.sync.aligned.m16n8k16.row.col.f16.f16.f16.f16 "
        "{%0,%1}, {%2,%3,%4,%5}, {%6,%7}, {%0,%1};"
        : "+r"(c[0]), "+r"(c[1])
        : "r"(a[0]), "r"(a[1]), "r"(a[2]), "r"(a[3]), "r"(b[0]), "r"(b[1]));
}
__device__ __forceinline__ unsigned h2u(float lo, float hi) {
    __half2 h = __floats2half2_rn(lo, hi);
    return *(unsigned*)&h;
}
__device__ __forceinline__ unsigned ex2h2(unsigned x) {   // packed fp16 2^x
    unsigned y;
    asm("ex2.approx.f16x2 %0, %1;" : "=r"(y) : "r"(x));
    return y;
}
__device__ __forceinline__ float ex2(float x) {
    float y;
    asm("ex2.approx.ftz.f32 %0, %1;" : "=f"(y) : "f"(x));
    return y;
}
__device__ __forceinline__ unsigned hsub2u(unsigned a, unsigned b) {
    __half2 r = __hsub2(*(__half2*)&a, *(__half2*)&b);
    return *(unsigned*)&r;
}
__device__ __forceinline__ void cpa16(unsigned dst, const void* src) {
    asm volatile("cp.async.cg.shared.global [%0], [%1], 16;" :: "r"(dst), "l"(src));
}
__device__ __forceinline__ void cpa_commit() {
    asm volatile("cp.async.commit_group;");
}

// ---- Kernel 1: fp32 -> fp16 conversion of K and V ----
__global__ __launch_bounds__(256)
void convert_kv(const float* __restrict__ K, const float* __restrict__ V) {
    const int i = blockIdx.x * 256 + threadIdx.x;   // one float4 per thread
    const int n4 = Bc * Lc * Hc * Dc / 4;
    if (i < n4) {
        float4 k4 = ((const float4*)K)[i];
        ((uint2*)gK)[i] = make_uint2(h2u(k4.x, k4.y), h2u(k4.z, k4.w));
        float4 v4 = ((const float4*)V)[i];
        ((uint2*)gV)[i] = make_uint2(h2u(v4.x, v4.y), h2u(v4.z, v4.w));
    }
}

// ---- Kernel 2: flash attention ----
__global__ __launch_bounds__(NT)
void fa_f16_pipe_kernel(const float* __restrict__ Qg, float* __restrict__ Og) {
    __shared__ union {
        struct {
            __half k[2][BN * SKH];
            __half v[2][BN * SKH];
        } s;
        __half q[BM * SKH];     // Q staging (prologue only; overlaps k/v)
    } sm;

    const int tid  = threadIdx.x;
    const int lane = tid & 31;
    const int w    = tid >> 5;        // warp 0..3
    const int gid  = lane >> 2;
    const int tig  = lane & 3;
    const int m0   = 16 * w;          // warp's 16-row block within the 64-row tile
    const int tq   = (gridDim.x - 1) - blockIdx.x;   // heavy CTAs first
    const int h    = blockIdx.y;
    const int b    = blockIdx.z;
    const int q0   = tq * BM;

    const int rowstride = Hc * Dc;    // 1024
    const size_t base = ((size_t)b * Lc * Hc + h) * (size_t)Dc;
    const float*  Qb = Qg + base;
    const __half* Kh = gK + base;
    const __half* Vh = gV + base;
    float*        Ob = Og + base;

    // ---- Stage Q (scale 1/8 and log2e folded), fragment to registers ----
    const float qscale = 0.125f * LOG2E;
    for (int i = tid; i < BM * 16; i += NT) {
        const int r = i >> 4;
        const int c = (i & 15) << 2;
        float4 v = *(const float4*)(Qb + (size_t)(q0 + r) * rowstride + c);
        *(uint2*)&sm.q[r * SKH + c] =
            make_uint2(h2u(v.x * qscale, v.y * qscale), h2u(v.z * qscale, v.w * qscale));
    }
    __syncthreads();

    unsigned qa[4][4];
    #pragma unroll
    for (int kt = 0; kt < 4; ++kt)
        ldsm4(qa[kt], sptr(&sm.q[(m0 + (lane & 15)) * SKH + 16 * kt + ((lane >> 4) << 3)]));
    __syncthreads();   // frags extracted before cp.async overwrites the union

    __half2 m_pack = __halves2half2(__ushort_as_half(0xFC00), __ushort_as_half(0xFC00));
    float l_[2] = {0.0f, 0.0f};
    float o[8][4];
    #pragma unroll
    for (int n = 0; n < 8; ++n)
        #pragma unroll
        for (int j = 0; j < 4; ++j) o[n][j] = 0.0f;

    const unsigned ones2[2] = {0x3C003C00u, 0x3C003C00u};   // fp16 1.0 x2

    // ---- Prologue: async-load tile 0 ----
    #pragma unroll
    for (int i = tid; i < 512; i += NT) {          // 64 rows x 8 chunks of 16B
        const int r = i >> 3, c = (i & 7) << 3;
        cpa16(sptr(&sm.s.k[0][r * SKH + c]), Kh + (size_t)r * rowstride + c);
        cpa16(sptr(&sm.s.v[0][r * SKH + c]), Vh + (size_t)r * rowstride + c);
    }
    cpa_commit();

    for (int t = 0; t <= tq; ++t) {
        const int buf = t & 1;

        asm volatile("cp.async.wait_group 0;");
        __syncthreads();   // publishes tile t; iter t-1 done with buf^1

        if (t < tq) {
            const int k1 = (t + 1) * BN;
            #pragma unroll
            for (int i = tid; i < 512; i += NT) {
                const int r = i >> 3, c = (i & 7) << 3;
                cpa16(sptr(&sm.s.k[buf ^ 1][r * SKH + c]),
                      Kh + (size_t)(k1 + r) * rowstride + c);
                cpa16(sptr(&sm.s.v[buf ^ 1][r * SKH + c]),
                      Vh + (size_t)(k1 + r) * rowstride + c);
            }
            cpa_commit();
        }

        // ---- GEMM1 (fp16 accum): S(16x64) = Q @ K^T, packed half2 ----
        unsigned s[8][2];
        #pragma unroll
        for (int n = 0; n < 8; ++n) { s[n][0] = 0u; s[n][1] = 0u; }

        #pragma unroll
        for (int kt = 0; kt < 4; ++kt) {
            const int k0 = 16 * kt;
            #pragma unroll
            for (int np = 0; np < 4; ++np) {
                unsigned br[4];
                ldsm4(br, sptr(&sm.s.k[buf][(16 * np + (lane & 7) + ((lane >> 4) << 3)) * SKH
                                           + k0 + (lane & 8)]));
                mma_f16h(s[2 * np],     qa[kt], br);
                mma_f16h(s[2 * np + 1], qa[kt], br + 2);
            }
        }

        // ---- Causal mask (diagonal tile only) ----
        if (t == tq) {
            const int r0g = m0 + gid, r1g = r0g + 8;   // within-tile rows
            const int cb  = 2 * tig;
            const __half NI = __ushort_as_half(0xFC00);
            #pragma unroll
            for (int n = 0; n < 8; ++n) {
                const int c0 = cb + 8 * n;
                __half2 v0 = *(__half2*)&s[n][0];
                __half2 v1 = *(__half2*)&s[n][1];
                if (c0     > r0g) v0.x = NI;
                if (c0 + 1 > r0g) v0.y = NI;
                if (c0     > r1g) v1.x = NI;
                if (c0 + 1 > r1g) v1.y = NI;
                s[n][0] = *(unsigned*)&v0;
                s[n][1] = *(unsigned*)&v1;
            }
        }

        // ---- Packed max reduction (rows gid, gid+8 together) ----
        __half2 a0 = *(__half2*)&s[0][0];
        __half2 a1 = *(__half2*)&s[0][1];
        #pragma unroll
        for (int n = 1; n < 8; ++n) {
            a0 = __hmax2(a0, *(__half2*)&s[n][0]);
            a1 = __hmax2(a1, *(__half2*)&s[n][1]);
        }
        __half2 mx = __halves2half2(__hmax(__low2half(a0), __high2half(a0)),
                                    __hmax(__low2half(a1), __high2half(a1)));
        {
            unsigned mu = *(unsigned*)&mx;
            unsigned t1 = __shfl_xor_sync(0xffffffffu, mu, 1);
            mx = __hmax2(mx, *(__half2*)&t1);
            mu = *(unsigned*)&mx;
            unsigned t2 = __shfl_xor_sync(0xffffffffu, mu, 2);
            mx = __hmax2(mx, *(__half2*)&t2);
        }
        const __half2 mn = __hmax2(m_pack, mx);
        const float al0 = ex2(__low2float(m_pack)  - __low2float(mn));
        const float al1 = ex2(__high2float(m_pack) - __high2float(mn));
        m_pack = mn;
        const __half2 mnb0h = __half2half2(__low2half(mn));
        const __half2 mnb1h = __half2half2(__high2half(mn));
        const unsigned mnb0 = *(const unsigned*)&mnb0h;
        const unsigned mnb1 = *(const unsigned*)&mnb1h;

        // Rescale O before accumulating this tile.
        #pragma unroll
        for (int n = 0; n < 8; ++n) {
            o[n][0] *= al0; o[n][1] *= al0;
            o[n][2] *= al1; o[n][3] *= al1;
        }

        // ---- exp fused into GEMM2: O += P @ V; rs = P @ 1 ----
        float rsacc[4] = {0.0f, 0.0f, 0.0f, 0.0f};
        #pragma unroll
        for (int kt = 0; kt < 4; ++kt) {
            const int k0 = 16 * kt;
            unsigned pa[4];
            pa[0] = ex2h2(hsub2u(s[2 * kt][0],     mnb0));
            pa[1] = ex2h2(hsub2u(s[2 * kt][1],     mnb1));
            pa[2] = ex2h2(hsub2u(s[2 * kt + 1][0], mnb0));
            pa[3] = ex2h2(hsub2u(s[2 * kt + 1][1], mnb1));
            mma_f16(rsacc, pa, ones2);
            #pragma unroll
            for (int np = 0; np < 4; ++np) {
                unsigned bv[4];
                ldsm4t(bv, sptr(&sm.s.v[buf][(k0 + (lane & 15)) * SKH
                                             + 16 * np + ((lane >> 4) << 3)]));
                mma_f16(o[2 * np],     pa, bv);
                mma_f16(o[2 * np + 1], pa, bv + 2);
            }
        }
        l_[0] = l_[0] * al0 + rsacc[0];
        l_[1] = l_[1] * al1 + rsacc[2];
    }

    // ---- Epilogue: normalize and store ----
    const float inv0 = 1.0f / l_[0];
    const float inv1 = 1.0f / l_[1];
    const int r0 = q0 + m0 + gid;
    const int r1 = r0 + 8;
    #pragma unroll
    for (int n = 0; n < 8; ++n) {
        const int c0 = 8 * n + 2 * tig;
        *(float2*)(Ob + (size_t)r0 * rowstride + c0) =
            make_float2(o[n][0] * inv0, o[n][1] * inv0);
        *(float2*)(Ob + (size_t)r1 * rowstride + c0) =
            make_float2(o[n][2] * inv1, o[n][3] * inv1);
    }
}

extern "C" void kernel_launch(void* const* d_in, const int* in_sizes, int n_in,
                              void* d_out, int out_size) {
    const float* q = (const float*)d_in[0];
    const float* k = (const float*)d_in[1];
    const float* v = (const float*)d_in[2];
    float* out = (float*)d_out;

    const int n4 = Bc * Lc * Hc * Dc / 4;
    convert_kv<<<(n4 + 255) / 256, 256>>>(k, v);

    dim3 grid(Lc / BM, Hc, Bc);   // (32, 16, 4)
    fa_f16_pipe_kernel<<<grid, NT>>>(q, out);
}

// round 13
// speedup vs baseline: 1.2835x; 1.2835x over previous
#include <cuda_runtime.h>
#include <cuda_fp16.h>

// FullAttention: causal MHA, B=4, L=2048, H=16, DK=64, fp32 I/O.
// Round 12: persistent CTAs (zigzag LPT over 1024 work items) +
//           tile-level software pipelining (GEMM1 of t+1 interleaved with
//           softmax/GEMM2 of t in one branch-free region). Math == R7/R9.

constexpr int Bc = 4, Lc = 2048, Hc = 16, Dc = 64;
constexpr int BM = 128;     // query rows per CTA work item
constexpr int BN = 64;      // key rows per tile
constexpr int NT = 256;     // 8 warps
constexpr int SKH = 72;     // smem row stride in halfs (144 B)
constexpr int PGRID = 304;  // persistent CTAs: 2 per SM x 152 SMs (GB300)
constexpr int NITEMS = 1024;  // 16 tq levels x 64 (b,h)
constexpr float LOG2E = 1.44269504f;

__device__ __half gK[(size_t)Bc * Lc * Hc * Dc];
__device__ __half gV[(size_t)Bc * Lc * Hc * Dc];

__device__ __forceinline__ unsigned sptr(const void* p) {
    return (unsigned)__cvta_generic_to_shared(p);
}
__device__ __forceinline__ void ldsm4(unsigned r[4], unsigned addr) {
    asm volatile("ldmatrix.sync.aligned.m8n8.x4.shared.b16 {%0,%1,%2,%3}, [%4];"
                 : "=r"(r[0]), "=r"(r[1]), "=r"(r[2]), "=r"(r[3]) : "r"(addr));
}
__device__ __forceinline__ void ldsm4t(unsigned r[4], unsigned addr) {
    asm volatile("ldmatrix.sync.aligned.m8n8.x4.trans.shared.b16 {%0,%1,%2,%3}, [%4];"
                 : "=r"(r[0]), "=r"(r[1]), "=r"(r[2]), "=r"(r[3]) : "r"(addr));
}
__device__ __forceinline__ void mma_f16(float c[4], const unsigned a[4], const unsigned b[2]) {
    asm volatile(
        "mma.sync.aligned.m16n8k16.row.col.f32.f16.f16.f32 "
        "{%0,%1,%2,%3}, {%4,%5,%6,%7}, {%8,%9}, {%0,%1,%2,%3};"
        : "+f"(c[0]), "+f"(c[1]), "+f"(c[2]), "+f"(c[3])
        : "r"(a[0]), "r"(a[1]), "r"(a[2]), "r"(a[3]), "r"(b[0]), "r"(b[1]));
}
__device__ __forceinline__ void mma_f16h(unsigned c[2], const unsigned a[4], const unsigned b[2]) {
    asm volatile(
        "mma.sync.aligned.m16n8k16.row.col.f16.f16.f16.f16 "
        "{%0,%1}, {%2,%3,%4,%5}, {%6,%7}, {%0,%1};"
        : "+r"(c[0]), "+r"(c[1])
        : "r"(a[0]), "r"(a[1]), "r"(a[2]), "r"(a[3]), "r"(b[0]), "r"(b[1]));
}
__device__ __forceinline__ unsigned h2u(float lo, float hi) {
    __half2 h = __floats2half2_rn(lo, hi);
    return *(unsigned*)&h;
}
__device__ __forceinline__ unsigned ex2h2(unsigned x) {
    unsigned y;
    asm("ex2.approx.f16x2 %0, %1;" : "=r"(y) : "r"(x));
    return y;
}
__device__ __forceinline__ float ex2(float x) {
    float y;
    asm("ex2.approx.ftz.f32 %0, %1;" : "=f"(y) : "f"(x));
    return y;
}
__device__ __forceinline__ unsigned hsub2u(unsigned a, unsigned b) {
    __half2 r = __hsub2(*(__half2*)&a, *(__half2*)&b);
    return *(unsigned*)&r;
}
__device__ __forceinline__ void cpa16(unsigned dst, const void* src) {
    asm volatile("cp.async.cg.shared.global [%0], [%1], 16;" :: "r"(dst), "l"(src));
}
__device__ __forceinline__ void cpa_commit() {
    asm volatile("cp.async.commit_group;");
}
__device__ __forceinline__ void cpa_wait0() {
    asm volatile("cp.async.wait_group 0;");
}

// ---- Kernel 1: fp32 -> fp16 conversion of K and V ----
__global__ __launch_bounds__(256)
void convert_kv(const float* __restrict__ K, const float* __restrict__ V) {
    const int i = blockIdx.x * 256 + threadIdx.x;
    const int n4 = Bc * Lc * Hc * Dc / 4;
    if (i < n4) {
        float4 k4 = ((const float4*)K)[i];
        ((uint2*)gK)[i] = make_uint2(h2u(k4.x, k4.y), h2u(k4.z, k4.w));
        float4 v4 = ((const float4*)V)[i];
        ((uint2*)gV)[i] = make_uint2(h2u(v4.x, v4.y), h2u(v4.z, v4.w));
    }
}

// One K/V tile (64 rows) via cp.async, one commit group.
__device__ __forceinline__ void load_tile(__half* kd, __half* vd,
                                          const __half* Kh, const __half* Vh,
                                          int k0r, int tid) {
    #pragma unroll
    for (int i = tid; i < 512; i += NT) {
        const int r = i >> 3, c = (i & 7) << 3;
        cpa16(sptr(&kd[r * SKH + c]), Kh + (size_t)(k0r + r) * (Hc * Dc) + c);
        cpa16(sptr(&vd[r * SKH + c]), Vh + (size_t)(k0r + r) * (Hc * Dc) + c);
    }
    cpa_commit();
}

// GEMM1 for one 16x64 warp strip: s = Q @ K^T (fp16 accum, packed half2).
__device__ __forceinline__ void gemm1_tile(unsigned s[8][2], const unsigned qa[4][4],
                                           const __half* kbuf, int lane) {
    #pragma unroll
    for (int n = 0; n < 8; ++n) { s[n][0] = 0u; s[n][1] = 0u; }
    #pragma unroll
    for (int kt = 0; kt < 4; ++kt) {
        const int k0 = 16 * kt;
        #pragma unroll
        for (int np = 0; np < 4; ++np) {
            unsigned br[4];
            ldsm4(br, sptr(&kbuf[(16 * np + (lane & 7) + ((lane >> 4) << 3)) * SKH
                                 + k0 + (lane & 8)]));
            mma_f16h(s[2 * np],     qa[kt], br);
            mma_f16h(s[2 * np + 1], qa[kt], br + 2);
        }
    }
}

// Softmax + O += P@V + l update for one tile (optionally causal-masked).
template<bool DOMASK>
__device__ __forceinline__ void tile_epilogue(
    unsigned s[8][2], float o[8][4], float l_[2], __half2& m_pack,
    const __half* vbuf, int lane, int r0g, int r1g, int cb)
{
    const unsigned ones2[2] = {0x3C003C00u, 0x3C003C00u};
    if (DOMASK) {
        const __half NI = __ushort_as_half(0xFC00);
        #pragma unroll
        for (int n = 0; n < 8; ++n) {
            const int c0 = cb + 8 * n;
            __half2 v0 = *(__half2*)&s[n][0];
            __half2 v1 = *(__half2*)&s[n][1];
            if (c0     > r0g) v0.x = NI;
            if (c0 + 1 > r0g) v0.y = NI;
            if (c0     > r1g) v1.x = NI;
            if (c0 + 1 > r1g) v1.y = NI;
            s[n][0] = *(unsigned*)&v0;
            s[n][1] = *(unsigned*)&v1;
        }
    }
    // packed max reduction
    __half2 a0 = *(__half2*)&s[0][0];
    __half2 a1 = *(__half2*)&s[0][1];
    #pragma unroll
    for (int n = 1; n < 8; ++n) {
        a0 = __hmax2(a0, *(__half2*)&s[n][0]);
        a1 = __hmax2(a1, *(__half2*)&s[n][1]);
    }
    __half2 mx = __halves2half2(__hmax(__low2half(a0), __high2half(a0)),
                                __hmax(__low2half(a1), __high2half(a1)));
    {
        unsigned mu = *(unsigned*)&mx;
        unsigned t1 = __shfl_xor_sync(0xffffffffu, mu, 1);
        mx = __hmax2(mx, *(__half2*)&t1);
        mu = *(unsigned*)&mx;
        unsigned t2 = __shfl_xor_sync(0xffffffffu, mu, 2);
        mx = __hmax2(mx, *(__half2*)&t2);
    }
    const __half2 mn = __hmax2(m_pack, mx);
    const float al0 = ex2(__low2float(m_pack)  - __low2float(mn));
    const float al1 = ex2(__high2float(m_pack) - __high2float(mn));
    m_pack = mn;
    const __half2 mnb0h = __half2half2(__low2half(mn));
    const __half2 mnb1h = __half2half2(__high2half(mn));
    const unsigned mnb0 = *(const unsigned*)&mnb0h;
    const unsigned mnb1 = *(const unsigned*)&mnb1h;

    #pragma unroll
    for (int n = 0; n < 8; ++n) {
        o[n][0] *= al0; o[n][1] *= al0;
        o[n][2] *= al1; o[n][3] *= al1;
    }

    float rsacc[4] = {0.0f, 0.0f, 0.0f, 0.0f};
    #pragma unroll
    for (int kt = 0; kt < 4; ++kt) {
        const int k0 = 16 * kt;
        unsigned pa[4];
        pa[0] = ex2h2(hsub2u(s[2 * kt][0],     mnb0));
        pa[1] = ex2h2(hsub2u(s[2 * kt][1],     mnb1));
        pa[2] = ex2h2(hsub2u(s[2 * kt + 1][0], mnb0));
        pa[3] = ex2h2(hsub2u(s[2 * kt + 1][1], mnb1));
        mma_f16(rsacc, pa, ones2);
        #pragma unroll
        for (int np = 0; np < 4; ++np) {
            unsigned bv[4];
            ldsm4t(bv, sptr(&vbuf[(k0 + (lane & 15)) * SKH
                                  + 16 * np + ((lane >> 4) << 3)]));
            mma_f16(o[2 * np],     pa, bv);
            mma_f16(o[2 * np + 1], pa, bv + 2);
        }
    }
    l_[0] = l_[0] * al0 + rsacc[0];
    l_[1] = l_[1] * al1 + rsacc[2];
}

// ---- Kernel 2: persistent flash attention ----
__global__ __launch_bounds__(NT, 2)
void fa_persist_kernel(const float* __restrict__ Qg, float* __restrict__ Og) {
    __shared__ union {
        struct {
            __half kb[2][BN * SKH];
            __half vb[3][BN * SKH];
        } s;
        __half q[BM * SKH];     // aliases kb[0..1] exactly (BM = 2*BN)
    } sm;

    const int tid  = threadIdx.x;
    const int lane = tid & 31;
    const int w    = tid >> 5;        // warp 0..7
    const int gid  = lane >> 2;
    const int tig  = lane & 3;
    const int m0   = 16 * w;
    const int p    = blockIdx.x;
    const int rowstride = Hc * Dc;    // 1024

    // Zigzag LPT: items sorted heavy-first (tq descending), boustrophedon rounds.
    for (int r = 0; r < 4; ++r) {
        const int item = (r & 1) ? ((r + 1) * PGRID - 1 - p) : (r * PGRID + p);
        if (item >= NITEMS) continue;
        const int tq = 15 - (item >> 6);
        const int bh = item & 63;
        const int q0 = tq * BM;
        const int tmax = 2 * tq + 1;

        const size_t base = ((size_t)(bh >> 4) * Lc * Hc + (bh & 15)) * (size_t)Dc;
        const float*  Qb = Qg + base;
        const __half* Kh = gK + base;
        const __half* Vh = gV + base;
        float*        Ob = Og + base;

        __syncthreads();   // previous item fully done before Q staging over kb

        // ---- Stage Q (scale 1/8 and log2e folded), fragment to registers ----
        const float qscale = 0.125f * LOG2E;
        for (int i = tid; i < BM * 16; i += NT) {
            const int rr = i >> 4;
            const int c  = (i & 15) << 2;
            float4 v = *(const float4*)(Qb + (size_t)(q0 + rr) * rowstride + c);
            *(uint2*)&sm.q[rr * SKH + c] =
                make_uint2(h2u(v.x * qscale, v.y * qscale), h2u(v.z * qscale, v.w * qscale));
        }
        __syncthreads();

        unsigned qa[4][4];
        #pragma unroll
        for (int kt = 0; kt < 4; ++kt)
            ldsm4(qa[kt], sptr(&sm.q[(m0 + (lane & 15)) * SKH + 16 * kt + ((lane >> 4) << 3)]));
        __syncthreads();   // frags extracted before cp.async overwrites the union

        // ---- Prologue: tile 0, then tile 1 in flight, GEMM1(0) ----
        load_tile(sm.s.kb[0], sm.s.vb[0], Kh, Vh, 0, tid);
        cpa_wait0();
        __syncthreads();
        load_tile(sm.s.kb[1], sm.s.vb[1], Kh, Vh, BN, tid);

        unsigned scur[8][2], snext[8][2];
        gemm1_tile(scur, qa, sm.s.kb[0], lane);

        __half2 m_pack = __halves2half2(__ushort_as_half(0xFC00), __ushort_as_half(0xFC00));
        float l_[2] = {0.0f, 0.0f};
        float o[8][4];
        #pragma unroll
        for (int n = 0; n < 8; ++n)
            #pragma unroll
            for (int j = 0; j < 4; ++j) o[n][j] = 0.0f;

        const int r0g = q0 + m0 + gid, r1g = r0g + 8;

        // ---- Main loop: branch-free; GEMM1(t+1) interleaves with softmax(t) ----
        for (int t = 0; t <= tmax - 2; ++t) {
            cpa_wait0();        // tile t+1 arrived
            __syncthreads();    // publish; all warps done with kb[t&1], vb[(t+2)%3]
            gemm1_tile(snext, qa, sm.s.kb[(t + 1) & 1], lane);
            load_tile(sm.s.kb[t & 1], sm.s.vb[(t + 2) % 3], Kh, Vh, (t + 2) * BN, tid);
            tile_epilogue<false>(scur, o, l_, m_pack, sm.s.vb[t % 3], lane, 0, 0, 0);
            #pragma unroll
            for (int n = 0; n < 8; ++n) { scur[n][0] = snext[n][0]; scur[n][1] = snext[n][1]; }
        }

        // ---- Peel t = tmax-1 (upper-half diagonal) ----
        {
            const int t = tmax - 1;
            cpa_wait0();
            __syncthreads();
            if (m0 >= 64)      // only lower-half warps have work on tile tmax
                gemm1_tile(snext, qa, sm.s.kb[tmax & 1], lane);
            tile_epilogue<true>(scur, o, l_, m_pack, sm.s.vb[t % 3], lane,
                                r0g, r1g, t * BN + 2 * tig);
            #pragma unroll
            for (int n = 0; n < 8; ++n) { scur[n][0] = snext[n][0]; scur[n][1] = snext[n][1]; }
        }

        // ---- Peel t = tmax (lower-half diagonal; upper half fully masked) ----
        if (m0 >= 64) {
            tile_epilogue<true>(scur, o, l_, m_pack, sm.s.vb[tmax % 3], lane,
                                r0g, r1g, tmax * BN + 2 * tig);
        }

        // ---- Epilogue: normalize and store ----
        const float inv0 = 1.0f / l_[0];
        const float inv1 = 1.0f / l_[1];
        #pragma unroll
        for (int n = 0; n < 8; ++n) {
            const int c0 = 8 * n + 2 * tig;
            *(float2*)(Ob + (size_t)r0g * rowstride + c0) =
                make_float2(o[n][0] * inv0, o[n][1] * inv0);
            *(float2*)(Ob + (size_t)r1g * rowstride + c0) =
                make_float2(o[n][2] * inv1, o[n][3] * inv1);
        }
    }
}

extern "C" void kernel_launch(void* const* d_in, const int* in_sizes, int n_in,
                              void* d_out, int out_size) {
    const float* q = (const float*)d_in[0];
    const float* k = (const float*)d_in[1];
    const float* v = (const float*)d_in[2];
    float* out = (float*)d_out;

    const int n4 = Bc * Lc * Hc * Dc / 4;
    convert_kv<<<(n4 + 255) / 256, 256>>>(k, v);

    fa_persist_kernel<<<PGRID, NT>>>(q, out);
}